// round 1
// baseline (speedup 1.0000x reference)
#include <cuda_runtime.h>
#include <cuda_bf16.h>
#include <math.h>

#define LSEQ 2048
#define DM 1024
#define NH 16
#define HD 64

// Scratch (device globals: no allocation allowed in kernel_launch)
__device__ float g_qkv[LSEQ * 3 * DM];   // [i][s][h][d] : i*3072 + s*1024 + h*64 + d
__device__ float g_att[LSEQ * DM];       // [i][h*64+d]

// ---------------------------------------------------------------------------
// C[M,N] = A[M,K] @ B[N,K]^T + bias[N]
// BM=BN=64, BK=16, 256 threads, 4x4 microtile.
// ---------------------------------------------------------------------------
__device__ __forceinline__ void gemm_nt_bias(
    const float* __restrict__ A, const float* __restrict__ B,
    const float* __restrict__ bias, float* __restrict__ C,
    int M, int N, int K)
{
    __shared__ float As[16][68];
    __shared__ float Bs[16][68];
    const int t  = threadIdx.x;
    const int tx = t & 15;
    const int ty = t >> 4;
    const int lr = t >> 2;          // 0..63 load row
    const int lc = (t & 3) * 4;     // 0,4,8,12 load col (k)
    const int m0 = blockIdx.y * 64;
    const int n0 = blockIdx.x * 64;

    float acc[4][4] = {};
    const float* Ap = A + (size_t)(m0 + lr) * K + lc;
    const float* Bp = B + (size_t)(n0 + lr) * K + lc;

    for (int k0 = 0; k0 < K; k0 += 16) {
        float4 a4 = *(const float4*)(Ap + k0);
        float4 b4 = *(const float4*)(Bp + k0);
        As[lc + 0][lr] = a4.x; As[lc + 1][lr] = a4.y;
        As[lc + 2][lr] = a4.z; As[lc + 3][lr] = a4.w;
        Bs[lc + 0][lr] = b4.x; Bs[lc + 1][lr] = b4.y;
        Bs[lc + 2][lr] = b4.z; Bs[lc + 3][lr] = b4.w;
        __syncthreads();
#pragma unroll
        for (int kk = 0; kk < 16; kk++) {
            float4 av = *(const float4*)&As[kk][ty * 4];
            float4 bv = *(const float4*)&Bs[kk][tx * 4];
            float ra[4] = {av.x, av.y, av.z, av.w};
            float rb[4] = {bv.x, bv.y, bv.z, bv.w};
#pragma unroll
            for (int r = 0; r < 4; r++)
#pragma unroll
                for (int c = 0; c < 4; c++)
                    acc[r][c] += ra[r] * rb[c];
        }
        __syncthreads();
    }

    const int col = n0 + tx * 4;
    float4 bi = *(const float4*)(bias + col);
#pragma unroll
    for (int r = 0; r < 4; r++) {
        int row = m0 + ty * 4 + r;
        float4 o;
        o.x = acc[r][0] + bi.x;
        o.y = acc[r][1] + bi.y;
        o.z = acc[r][2] + bi.z;
        o.w = acc[r][3] + bi.w;
        *(float4*)(C + (size_t)row * N + col) = o;
    }
}

__global__ void __launch_bounds__(256)
k_gemm_qkv(const float* __restrict__ x, const float* __restrict__ W,
           const float* __restrict__ b)
{
    gemm_nt_bias(x, W, b, g_qkv, LSEQ, 3 * DM, DM);
}

__global__ void __launch_bounds__(256)
k_gemm_out(const float* __restrict__ W, const float* __restrict__ b,
           float* __restrict__ out)
{
    gemm_nt_bias(g_att, W, b, out, LSEQ, DM, DM);
}

// ---------------------------------------------------------------------------
// Fused attention: one CTA per (q-tile of 64 rows, head).
// Flash-style online softmax over 32 j-tiles of 64.
// smem: Qs[d][i], Ks[d][j]  (d-major for QK^T reduction)
//       Vs[j][d], Ps[j][i]  (j-major for PV reduction)
// ---------------------------------------------------------------------------
#define TS 68   // padded stride (68*4B = 272B, 16B-aligned rows)

__global__ void __launch_bounds__(256)
k_attn(const float* __restrict__ pb, const float* __restrict__ gate)
{
    extern __shared__ float smem[];
    float* Qs = smem;
    float* Ks = Qs + 64 * TS;
    float* Vs = Ks + 64 * TS;
    float* Ps = Vs + 64 * TS;

    const int t  = threadIdx.x;
    const int tx = t & 15;
    const int ty = t >> 4;
    const int h  = blockIdx.y;
    const int i0 = blockIdx.x * 64;
    const float gh = gate[h];
    const float scale = 0.125f;   // 1/sqrt(64)

    const int lrow = t >> 4;        // 0..15 (stride 16 over rows)
    const int ld0  = (t & 15) * 4;  // 0..60 dims, float4

    // Load Q tile (pre-scaled), transposed to d-major
    for (int rr = lrow; rr < 64; rr += 16) {
        float4 q4 = *(const float4*)&g_qkv[(size_t)(i0 + rr) * 3072 + h * 64 + ld0];
        Qs[(ld0 + 0) * TS + rr] = q4.x * scale;
        Qs[(ld0 + 1) * TS + rr] = q4.y * scale;
        Qs[(ld0 + 2) * TS + rr] = q4.z * scale;
        Qs[(ld0 + 3) * TS + rr] = q4.w * scale;
    }

    float m_i[4], l_i[4], o[4][4] = {};
#pragma unroll
    for (int r = 0; r < 4; r++) { m_i[r] = -1e30f; l_i[r] = 0.0f; }

    for (int jb = 0; jb < LSEQ / 64; jb++) {
        const int j0 = jb * 64;
        // Load K (transposed to d-major) and V (j-major)
        for (int rr = lrow; rr < 64; rr += 16) {
            float4 k4 = *(const float4*)&g_qkv[(size_t)(j0 + rr) * 3072 + 1024 + h * 64 + ld0];
            Ks[(ld0 + 0) * TS + rr] = k4.x;
            Ks[(ld0 + 1) * TS + rr] = k4.y;
            Ks[(ld0 + 2) * TS + rr] = k4.z;
            Ks[(ld0 + 3) * TS + rr] = k4.w;
            float4 v4 = *(const float4*)&g_qkv[(size_t)(j0 + rr) * 3072 + 2048 + h * 64 + ld0];
            *(float4*)&Vs[rr * TS + ld0] = v4;
        }
        __syncthreads();

        // S = (Q*scale) @ K^T
        float s[4][4] = {};
#pragma unroll
        for (int d = 0; d < 64; d++) {
            float4 av = *(const float4*)&Qs[d * TS + ty * 4];
            float4 bv = *(const float4*)&Ks[d * TS + tx * 4];
            float ra[4] = {av.x, av.y, av.z, av.w};
            float rb[4] = {bv.x, bv.y, bv.z, bv.w};
#pragma unroll
            for (int r = 0; r < 4; r++)
#pragma unroll
                for (int c = 0; c < 4; c++)
                    s[r][c] += ra[r] * rb[c];
        }

        // + gate * pair_bias   (coalesced float4 reads, 256MB total once)
#pragma unroll
        for (int r = 0; r < 4; r++) {
            const float4 bb = *(const float4*)&pb[((size_t)h * LSEQ + (i0 + ty * 4 + r)) * LSEQ + j0 + tx * 4];
            s[r][0] += gh * bb.x;
            s[r][1] += gh * bb.y;
            s[r][2] += gh * bb.z;
            s[r][3] += gh * bb.w;
        }

        // Online softmax (row groups = 16 lanes sharing ty; xor-shuffle reduce)
#pragma unroll
        for (int r = 0; r < 4; r++) {
            float mr = fmaxf(fmaxf(s[r][0], s[r][1]), fmaxf(s[r][2], s[r][3]));
#pragma unroll
            for (int off = 8; off >= 1; off >>= 1)
                mr = fmaxf(mr, __shfl_xor_sync(0xffffffffu, mr, off));
            float m_new = fmaxf(m_i[r], mr);
            float alpha = __expf(m_i[r] - m_new);
            m_i[r] = m_new;
            float sum = 0.0f;
#pragma unroll
            for (int c = 0; c < 4; c++) {
                float p = __expf(s[r][c] - m_new);
                s[r][c] = p;
                sum += p;
            }
#pragma unroll
            for (int off = 8; off >= 1; off >>= 1)
                sum += __shfl_xor_sync(0xffffffffu, sum, off);
            l_i[r] = l_i[r] * alpha + sum;
#pragma unroll
            for (int c = 0; c < 4; c++) o[r][c] *= alpha;
            // store P transposed -> Ps[j][i]
#pragma unroll
            for (int c = 0; c < 4; c++)
                Ps[(tx * 4 + c) * TS + ty * 4 + r] = s[r][c];
        }
        __syncthreads();

        // O += P @ V
#pragma unroll
        for (int j = 0; j < 64; j++) {
            float4 pv = *(const float4*)&Ps[j * TS + ty * 4];
            float4 vv = *(const float4*)&Vs[j * TS + tx * 4];
            float rp[4] = {pv.x, pv.y, pv.z, pv.w};
            float rv[4] = {vv.x, vv.y, vv.z, vv.w};
#pragma unroll
            for (int r = 0; r < 4; r++)
#pragma unroll
                for (int c = 0; c < 4; c++)
                    o[r][c] += rp[r] * rv[c];
        }
        __syncthreads();
    }

    // normalize + write [i][h*64+d]
#pragma unroll
    for (int r = 0; r < 4; r++) {
        float inv = 1.0f / l_i[r];
        float4 ov;
        ov.x = o[r][0] * inv;
        ov.y = o[r][1] * inv;
        ov.z = o[r][2] * inv;
        ov.w = o[r][3] * inv;
        *(float4*)&g_att[(size_t)(i0 + ty * 4 + r) * DM + h * 64 + tx * 4] = ov;
    }
}

// ---------------------------------------------------------------------------
extern "C" void kernel_launch(void* const* d_in, const int* in_sizes, int n_in,
                              void* d_out, int out_size)
{
    const float* x    = (const float*)d_in[0];
    const float* pb   = (const float*)d_in[1];
    const float* gate = (const float*)d_in[2];
    const float* Wqkv = (const float*)d_in[3];
    const float* bqkv = (const float*)d_in[4];
    const float* Wout = (const float*)d_in[5];
    const float* bout = (const float*)d_in[6];
    float* out = (float*)d_out;

    // QKV projection: [2048,1024] @ [3072,1024]^T
    k_gemm_qkv<<<dim3((3 * DM) / 64, LSEQ / 64), 256>>>(x, Wqkv, bqkv);

    // Fused attention
    const int smem_bytes = 4 * 64 * TS * (int)sizeof(float);  // 69632
    cudaFuncSetAttribute(k_attn, cudaFuncAttributeMaxDynamicSharedMemorySize, smem_bytes);
    k_attn<<<dim3(LSEQ / 64, NH), 256, smem_bytes>>>(pb, gate);

    // Output projection: [2048,1024] @ [1024,1024]^T
    k_gemm_out<<<dim3(DM / 64, LSEQ / 64), 256>>>(Wout, bout, out);
}

// round 2
// speedup vs baseline: 1.2422x; 1.2422x over previous
#include <cuda_runtime.h>
#include <cuda_bf16.h>
#include <math.h>

#define LSEQ 2048
#define DM 1024
#define NH 16
#define HD 64

// Scratch (device globals: no allocation allowed in kernel_launch)
__device__ float g_qkv[LSEQ * 3 * DM];   // [i][s][h][d] : i*3072 + s*1024 + h*64 + d
__device__ float g_att[LSEQ * DM];       // [i][h*64+d]

// ---------------------------------------------------------------------------
// C[M,N] = A[M,K] @ B[N,K]^T + bias[N]
// BM=BN=128, BK=8, 256 threads, 8x8 microtile, double-buffered smem.
// ---------------------------------------------------------------------------
__device__ __forceinline__ void gemm_nt_bias(
    const float* __restrict__ A, const float* __restrict__ B,
    const float* __restrict__ bias, float* __restrict__ C,
    int N, int K)
{
    __shared__ __align__(16) float As[2][8][132];
    __shared__ __align__(16) float Bs[2][8][132];
    const int t  = threadIdx.x;
    const int tx = t & 15;
    const int ty = t >> 4;
    const int lr = t >> 1;          // 0..127 load row
    const int lk = (t & 1) * 4;     // 0 or 4 (k offset)
    const int m0 = blockIdx.y * 128;
    const int n0 = blockIdx.x * 128;

    const float* Ap = A + (size_t)(m0 + lr) * K + lk;
    const float* Bp = B + (size_t)(n0 + lr) * K + lk;

    float4 a4 = *(const float4*)Ap;
    float4 b4 = *(const float4*)Bp;
    As[0][lk + 0][lr] = a4.x; As[0][lk + 1][lr] = a4.y;
    As[0][lk + 2][lr] = a4.z; As[0][lk + 3][lr] = a4.w;
    Bs[0][lk + 0][lr] = b4.x; Bs[0][lk + 1][lr] = b4.y;
    Bs[0][lk + 2][lr] = b4.z; Bs[0][lk + 3][lr] = b4.w;
    __syncthreads();

    float acc[8][8] = {};
    const int nk = K / 8;
    for (int kb = 0; kb < nk; kb++) {
        const int cur = kb & 1;
        if (kb + 1 < nk) {
            a4 = *(const float4*)(Ap + (size_t)(kb + 1) * 8);
            b4 = *(const float4*)(Bp + (size_t)(kb + 1) * 8);
        }
#pragma unroll
        for (int kk = 0; kk < 8; kk++) {
            float ra[8], rb[8];
            *(float4*)&ra[0] = *(const float4*)&As[cur][kk][ty * 8];
            *(float4*)&ra[4] = *(const float4*)&As[cur][kk][ty * 8 + 4];
            *(float4*)&rb[0] = *(const float4*)&Bs[cur][kk][tx * 8];
            *(float4*)&rb[4] = *(const float4*)&Bs[cur][kk][tx * 8 + 4];
#pragma unroll
            for (int r = 0; r < 8; r++)
#pragma unroll
                for (int c = 0; c < 8; c++)
                    acc[r][c] += ra[r] * rb[c];
        }
        if (kb + 1 < nk) {
            const int nxt = cur ^ 1;
            As[nxt][lk + 0][lr] = a4.x; As[nxt][lk + 1][lr] = a4.y;
            As[nxt][lk + 2][lr] = a4.z; As[nxt][lk + 3][lr] = a4.w;
            Bs[nxt][lk + 0][lr] = b4.x; Bs[nxt][lk + 1][lr] = b4.y;
            Bs[nxt][lk + 2][lr] = b4.z; Bs[nxt][lk + 3][lr] = b4.w;
        }
        __syncthreads();
    }

    float bi[8];
    *(float4*)&bi[0] = *(const float4*)(bias + n0 + tx * 8);
    *(float4*)&bi[4] = *(const float4*)(bias + n0 + tx * 8 + 4);
#pragma unroll
    for (int r = 0; r < 8; r++) {
        float* Crow = C + (size_t)(m0 + ty * 8 + r) * N + n0 + tx * 8;
        float4 o0, o1;
        o0.x = acc[r][0] + bi[0]; o0.y = acc[r][1] + bi[1];
        o0.z = acc[r][2] + bi[2]; o0.w = acc[r][3] + bi[3];
        o1.x = acc[r][4] + bi[4]; o1.y = acc[r][5] + bi[5];
        o1.z = acc[r][6] + bi[6]; o1.w = acc[r][7] + bi[7];
        *(float4*)Crow       = o0;
        *(float4*)(Crow + 4) = o1;
    }
}

__global__ void __launch_bounds__(256)
k_gemm_qkv(const float* __restrict__ x, const float* __restrict__ W,
           const float* __restrict__ b)
{
    gemm_nt_bias(x, W, b, g_qkv, 3 * DM, DM);
}

__global__ void __launch_bounds__(256)
k_gemm_out(const float* __restrict__ W, const float* __restrict__ b,
           float* __restrict__ out)
{
    gemm_nt_bias(g_att, W, b, out, DM, DM);
}

// ---------------------------------------------------------------------------
// Fused attention: one CTA per (q-tile of 128 rows, head), j-tiles of 128.
// S microtile 8x8 (ty=i-group, tx=j-group); PV microtile 8(i)x4(d).
// smem: Qs[d][i] 64x128, Ks[d][j] 64x128 (d-major), Vs[j][d] 128x68,
//       Ps[i][j] 128x132.
// ---------------------------------------------------------------------------
#define QS_N   (64 * 128)
#define VS_STR 68
#define PS_STR 132

__global__ void __launch_bounds__(256, 1)
k_attn(const float* __restrict__ pb, const float* __restrict__ gate)
{
    extern __shared__ float sm[];
    float* Qs = sm;                       // [64][128]
    float* Ks = Qs + QS_N;                // [64][128]
    float* Vs = Ks + QS_N;                // [128][68]
    float* Ps = Vs + 128 * VS_STR;        // [128][132]

    const int t  = threadIdx.x;
    const int tx = t & 15;
    const int ty = t >> 4;
    const int h  = blockIdx.y;
    const int i0 = blockIdx.x * 128;
    const float gh = gate[h];
    const float scale = 0.125f;   // 1/sqrt(64)

    const int lrow = t >> 1;        // 0..127
    const int ld0  = (t & 1) * 32;  // 0 or 32 (d offset, 32 floats each)

    // Load Q tile (pre-scaled), transposed to d-major
    {
        const float* src = g_qkv + (size_t)(i0 + lrow) * 3072 + h * 64 + ld0;
#pragma unroll
        for (int u = 0; u < 8; u++) {
            float4 q4 = *(const float4*)(src + u * 4);
            const int d = ld0 + u * 4;
            Qs[(d + 0) * 128 + lrow] = q4.x * scale;
            Qs[(d + 1) * 128 + lrow] = q4.y * scale;
            Qs[(d + 2) * 128 + lrow] = q4.z * scale;
            Qs[(d + 3) * 128 + lrow] = q4.w * scale;
        }
    }

    float m_i[8], l_i[8], o[8][4] = {};
#pragma unroll
    for (int r = 0; r < 8; r++) { m_i[r] = -1e30f; l_i[r] = 0.0f; }

    for (int jb = 0; jb < LSEQ / 128; jb++) {
        const int j0 = jb * 128;
        // Load K (transposed, d-major) and V (j-major)
        {
            const float* ksrc = g_qkv + (size_t)(j0 + lrow) * 3072 + 1024 + h * 64 + ld0;
            const float* vsrc = ksrc + 1024;
#pragma unroll
            for (int u = 0; u < 8; u++) {
                float4 k4 = *(const float4*)(ksrc + u * 4);
                const int d = ld0 + u * 4;
                Ks[(d + 0) * 128 + lrow] = k4.x;
                Ks[(d + 1) * 128 + lrow] = k4.y;
                Ks[(d + 2) * 128 + lrow] = k4.z;
                Ks[(d + 3) * 128 + lrow] = k4.w;
                float4 v4 = *(const float4*)(vsrc + u * 4);
                *(float4*)&Vs[lrow * VS_STR + ld0 + u * 4] = v4;
            }
        }
        __syncthreads();

        // S = (Q*scale) @ K^T   (8x8 per thread)
        float s[8][8] = {};
#pragma unroll 8
        for (int kk = 0; kk < 64; kk++) {
            float ra[8], rb[8];
            *(float4*)&ra[0] = *(const float4*)&Qs[kk * 128 + ty * 8];
            *(float4*)&ra[4] = *(const float4*)&Qs[kk * 128 + ty * 8 + 4];
            *(float4*)&rb[0] = *(const float4*)&Ks[kk * 128 + tx * 8];
            *(float4*)&rb[4] = *(const float4*)&Ks[kk * 128 + tx * 8 + 4];
#pragma unroll
            for (int r = 0; r < 8; r++)
#pragma unroll
                for (int c = 0; c < 8; c++)
                    s[r][c] += ra[r] * rb[c];
        }

        // + gate * pair_bias (coalesced float4)
        {
            const float* pbp = pb + ((size_t)h * LSEQ + (i0 + ty * 8)) * LSEQ + j0 + tx * 8;
#pragma unroll
            for (int r = 0; r < 8; r++) {
                float4 b0 = *(const float4*)(pbp + (size_t)r * LSEQ);
                float4 b1 = *(const float4*)(pbp + (size_t)r * LSEQ + 4);
                s[r][0] += gh * b0.x; s[r][1] += gh * b0.y;
                s[r][2] += gh * b0.z; s[r][3] += gh * b0.w;
                s[r][4] += gh * b1.x; s[r][5] += gh * b1.y;
                s[r][6] += gh * b1.z; s[r][7] += gh * b1.w;
            }
        }

        // Online softmax (row split across 16 tx lanes; xor-shuffle reduce)
#pragma unroll
        for (int r = 0; r < 8; r++) {
            float mr = s[r][0];
#pragma unroll
            for (int c = 1; c < 8; c++) mr = fmaxf(mr, s[r][c]);
#pragma unroll
            for (int off = 8; off >= 1; off >>= 1)
                mr = fmaxf(mr, __shfl_xor_sync(0xffffffffu, mr, off));
            const float m_new = fmaxf(m_i[r], mr);
            const float alpha = __expf(m_i[r] - m_new);
            m_i[r] = m_new;
            float sum = 0.0f;
#pragma unroll
            for (int c = 0; c < 8; c++) {
                const float p = __expf(s[r][c] - m_new);
                s[r][c] = p;
                sum += p;
            }
#pragma unroll
            for (int off = 8; off >= 1; off >>= 1)
                sum += __shfl_xor_sync(0xffffffffu, sum, off);
            l_i[r] = l_i[r] * alpha + sum;
#pragma unroll
            for (int c = 0; c < 4; c++) o[r][c] *= alpha;
            float4 p0, p1;
            p0.x = s[r][0]; p0.y = s[r][1]; p0.z = s[r][2]; p0.w = s[r][3];
            p1.x = s[r][4]; p1.y = s[r][5]; p1.z = s[r][6]; p1.w = s[r][7];
            *(float4*)&Ps[(ty * 8 + r) * PS_STR + tx * 8]     = p0;
            *(float4*)&Ps[(ty * 8 + r) * PS_STR + tx * 8 + 4] = p1;
        }
        __syncthreads();

        // O += P @ V  (j-vectorized by 4: 12 LDS.128 per 128 FMA)
#pragma unroll 4
        for (int j = 0; j < 128; j += 4) {
            float4 v0 = *(const float4*)&Vs[(j + 0) * VS_STR + tx * 4];
            float4 v1 = *(const float4*)&Vs[(j + 1) * VS_STR + tx * 4];
            float4 v2 = *(const float4*)&Vs[(j + 2) * VS_STR + tx * 4];
            float4 v3 = *(const float4*)&Vs[(j + 3) * VS_STR + tx * 4];
#pragma unroll
            for (int r = 0; r < 8; r++) {
                float4 p4 = *(const float4*)&Ps[(ty * 8 + r) * PS_STR + j];
                o[r][0] += p4.x * v0.x; o[r][1] += p4.x * v0.y;
                o[r][2] += p4.x * v0.z; o[r][3] += p4.x * v0.w;
                o[r][0] += p4.y * v1.x; o[r][1] += p4.y * v1.y;
                o[r][2] += p4.y * v1.z; o[r][3] += p4.y * v1.w;
                o[r][0] += p4.z * v2.x; o[r][1] += p4.z * v2.y;
                o[r][2] += p4.z * v2.z; o[r][3] += p4.z * v2.w;
                o[r][0] += p4.w * v3.x; o[r][1] += p4.w * v3.y;
                o[r][2] += p4.w * v3.z; o[r][3] += p4.w * v3.w;
            }
        }
        __syncthreads();
    }

    // normalize + write [i][h*64+d]
#pragma unroll
    for (int r = 0; r < 8; r++) {
        const float inv = 1.0f / l_i[r];
        float4 ov;
        ov.x = o[r][0] * inv;
        ov.y = o[r][1] * inv;
        ov.z = o[r][2] * inv;
        ov.w = o[r][3] * inv;
        *(float4*)&g_att[(size_t)(i0 + ty * 8 + r) * DM + h * 64 + tx * 4] = ov;
    }
}

// ---------------------------------------------------------------------------
extern "C" void kernel_launch(void* const* d_in, const int* in_sizes, int n_in,
                              void* d_out, int out_size)
{
    const float* x    = (const float*)d_in[0];
    const float* pb   = (const float*)d_in[1];
    const float* gate = (const float*)d_in[2];
    const float* Wqkv = (const float*)d_in[3];
    const float* bqkv = (const float*)d_in[4];
    const float* Wout = (const float*)d_in[5];
    const float* bout = (const float*)d_in[6];
    float* out = (float*)d_out;

    // QKV projection: [2048,1024] @ [3072,1024]^T
    k_gemm_qkv<<<dim3((3 * DM) / 128, LSEQ / 128), 256>>>(x, Wqkv, bqkv);

    // Fused attention
    const int smem_bytes = (2 * QS_N + 128 * VS_STR + 128 * PS_STR) * (int)sizeof(float); // 167936
    cudaFuncSetAttribute(k_attn, cudaFuncAttributeMaxDynamicSharedMemorySize, smem_bytes);
    k_attn<<<dim3(LSEQ / 128, NH), 256, smem_bytes>>>(pb, gate);

    // Output projection: [2048,1024] @ [1024,1024]^T
    k_gemm_out<<<dim3(DM / 128, LSEQ / 128), 256>>>(Wout, bout, out);
}

// round 11
// speedup vs baseline: 1.3551x; 1.0909x over previous
#include <cuda_runtime.h>
#include <math.h>

#define LSEQ 2048
#define DM 1024
#define NH 16

// Scratch (device globals: no allocation allowed in kernel_launch)
__device__ float g_qkv[LSEQ * 3 * DM];   // [i][s*1024 + h*64 + d]
__device__ float g_att[LSEQ * DM];       // [i][h*64+d]

// Bank-conflict-free column mapping: pad 4 floats every 32 columns.
// Range: smap(127) = 139, so row stride must be >= 140.
__device__ __forceinline__ int smap(int c) { return c + ((c >> 5) << 2); }

#define GSTR 140   // 128 cols + 3 pads of 4 (max mapped index 139)

// ---------------------------------------------------------------------------
// C[M,N] = A[M,K] @ B[N,K]^T + bias[N]
// BM=BN=128, BK=8, 256 threads, 8x8 microtile, double-buffered smem.
// Conflict-free smem layout via smap().
// ---------------------------------------------------------------------------
__device__ __forceinline__ void gemm_nt_bias(
    const float* __restrict__ A, const float* __restrict__ B,
    const float* __restrict__ bias, float* __restrict__ C,
    int N, int K)
{
    __shared__ __align__(16) float As[2][8][GSTR];
    __shared__ __align__(16) float Bs[2][8][GSTR];
    const int t  = threadIdx.x;
    const int tx = t & 15;
    const int ty = t >> 4;
    const int lr = t >> 1;          // 0..127 load row
    const int lk = (t & 1) * 4;     // 0 or 4 (k offset)
    const int m0 = blockIdx.y * 128;
    const int n0 = blockIdx.x * 128;
    const int lrm = smap(lr);       // mapped store column (<= 139)

    const float* Ap = A + (size_t)(m0 + lr) * K + lk;
    const float* Bp = B + (size_t)(n0 + lr) * K + lk;

    float4 a4 = *(const float4*)Ap;
    float4 b4 = *(const float4*)Bp;
    As[0][lk + 0][lrm] = a4.x; As[0][lk + 1][lrm] = a4.y;
    As[0][lk + 2][lrm] = a4.z; As[0][lk + 3][lrm] = a4.w;
    Bs[0][lk + 0][lrm] = b4.x; Bs[0][lk + 1][lrm] = b4.y;
    Bs[0][lk + 2][lrm] = b4.z; Bs[0][lk + 3][lrm] = b4.w;
    __syncthreads();

    float acc[8][8] = {};
    const int ra0 = smap(ty * 8);   // mapped read cols (contiguous inside 32-block)
    const int rb0 = smap(tx * 8);
    const int nk = K / 8;
    for (int kb = 0; kb < nk; kb++) {
        const int cur = kb & 1;
        if (kb + 1 < nk) {
            a4 = *(const float4*)(Ap + (size_t)(kb + 1) * 8);
            b4 = *(const float4*)(Bp + (size_t)(kb + 1) * 8);
        }
#pragma unroll
        for (int kk = 0; kk < 8; kk++) {
            float ra[8], rb[8];
            *(float4*)&ra[0] = *(const float4*)&As[cur][kk][ra0];
            *(float4*)&ra[4] = *(const float4*)&As[cur][kk][ra0 + 4];
            *(float4*)&rb[0] = *(const float4*)&Bs[cur][kk][rb0];
            *(float4*)&rb[4] = *(const float4*)&Bs[cur][kk][rb0 + 4];
#pragma unroll
            for (int r = 0; r < 8; r++)
#pragma unroll
                for (int c = 0; c < 8; c++)
                    acc[r][c] += ra[r] * rb[c];
        }
        if (kb + 1 < nk) {
            const int nxt = cur ^ 1;
            As[nxt][lk + 0][lrm] = a4.x; As[nxt][lk + 1][lrm] = a4.y;
            As[nxt][lk + 2][lrm] = a4.z; As[nxt][lk + 3][lrm] = a4.w;
            Bs[nxt][lk + 0][lrm] = b4.x; Bs[nxt][lk + 1][lrm] = b4.y;
            Bs[nxt][lk + 2][lrm] = b4.z; Bs[nxt][lk + 3][lrm] = b4.w;
        }
        __syncthreads();
    }

    float bi[8];
    *(float4*)&bi[0] = *(const float4*)(bias + n0 + tx * 8);
    *(float4*)&bi[4] = *(const float4*)(bias + n0 + tx * 8 + 4);
#pragma unroll
    for (int r = 0; r < 8; r++) {
        float* Crow = C + (size_t)(m0 + ty * 8 + r) * N + n0 + tx * 8;
        float4 o0, o1;
        o0.x = acc[r][0] + bi[0]; o0.y = acc[r][1] + bi[1];
        o0.z = acc[r][2] + bi[2]; o0.w = acc[r][3] + bi[3];
        o1.x = acc[r][4] + bi[4]; o1.y = acc[r][5] + bi[5];
        o1.z = acc[r][6] + bi[6]; o1.w = acc[r][7] + bi[7];
        *(float4*)Crow       = o0;
        *(float4*)(Crow + 4) = o1;
    }
}

__global__ void __launch_bounds__(256, 2)
k_gemm_qkv(const float* __restrict__ x, const float* __restrict__ W,
           const float* __restrict__ b)
{
    gemm_nt_bias(x, W, b, g_qkv, 3 * DM, DM);
}

__global__ void __launch_bounds__(256, 2)
k_gemm_out(const float* __restrict__ W, const float* __restrict__ b,
           float* __restrict__ out)
{
    gemm_nt_bias(g_att, W, b, out, DM, DM);
}

// ---------------------------------------------------------------------------
// Fused attention (R2 structure): one CTA per (q-tile 128, head), j-tiles 128.
// Qs/Ks d-major with conflict-free smap columns (stride 140).
// Vs[j][d] stride 68 (phase-clean), Ps[i][j] stride 132 (broadcast reads).
// ---------------------------------------------------------------------------
#define QK_STR 140
#define QS_N   (64 * QK_STR)
#define VS_STR 68
#define PS_STR 132

__global__ void __launch_bounds__(256, 1)
k_attn(const float* __restrict__ pb, const float* __restrict__ gate)
{
    extern __shared__ float smf[];
    float* Qs = smf;                      // [64][140] d-major (mapped cols)
    float* Ks = Qs + QS_N;                // [64][140] d-major (mapped cols)
    float* Vs = Ks + QS_N;                // [128][68] j-major
    float* Ps = Vs + 128 * VS_STR;        // [128][132] i-major

    const int t  = threadIdx.x;
    const int tx = t & 15;
    const int ty = t >> 4;
    const int h  = blockIdx.y;
    const int i0 = blockIdx.x * 128;
    const float gh = gate[h];
    const float scale = 0.125f;

    const int lrow = t >> 1;
    const int ld0  = (t & 1) * 32;
    const int lrowm = smap(lrow);         // mapped i/j column (<= 139)

    {
        const float* src = g_qkv + (size_t)(i0 + lrow) * 3072 + h * 64 + ld0;
#pragma unroll
        for (int u = 0; u < 8; u++) {
            float4 q4 = *(const float4*)(src + u * 4);
            const int d = ld0 + u * 4;
            Qs[(d + 0) * QK_STR + lrowm] = q4.x * scale;
            Qs[(d + 1) * QK_STR + lrowm] = q4.y * scale;
            Qs[(d + 2) * QK_STR + lrowm] = q4.z * scale;
            Qs[(d + 3) * QK_STR + lrowm] = q4.w * scale;
        }
    }

    float m_i[8], l_i[8], o[8][4] = {};
#pragma unroll
    for (int r = 0; r < 8; r++) { m_i[r] = -1e30f; l_i[r] = 0.0f; }

    const int ra0 = smap(ty * 8);
    const int rb0 = smap(tx * 8);

    for (int jb = 0; jb < LSEQ / 128; jb++) {
        const int j0 = jb * 128;
        {
            const float* ksrc = g_qkv + (size_t)(j0 + lrow) * 3072 + 1024 + h * 64 + ld0;
            const float* vsrc = ksrc + 1024;
#pragma unroll
            for (int u = 0; u < 8; u++) {
                float4 k4 = *(const float4*)(ksrc + u * 4);
                const int d = ld0 + u * 4;
                Ks[(d + 0) * QK_STR + lrowm] = k4.x;
                Ks[(d + 1) * QK_STR + lrowm] = k4.y;
                Ks[(d + 2) * QK_STR + lrowm] = k4.z;
                Ks[(d + 3) * QK_STR + lrowm] = k4.w;
                float4 v4 = *(const float4*)(vsrc + u * 4);
                *(float4*)&Vs[lrow * VS_STR + ld0 + u * 4] = v4;
            }
        }
        __syncthreads();

        float s[8][8] = {};
#pragma unroll 8
        for (int kk = 0; kk < 64; kk++) {
            float ra[8], rb[8];
            *(float4*)&ra[0] = *(const float4*)&Qs[kk * QK_STR + ra0];
            *(float4*)&ra[4] = *(const float4*)&Qs[kk * QK_STR + ra0 + 4];
            *(float4*)&rb[0] = *(const float4*)&Ks[kk * QK_STR + rb0];
            *(float4*)&rb[4] = *(const float4*)&Ks[kk * QK_STR + rb0 + 4];
#pragma unroll
            for (int r = 0; r < 8; r++)
#pragma unroll
                for (int c = 0; c < 8; c++)
                    s[r][c] += ra[r] * rb[c];
        }

        {
            const float* pbp = pb + ((size_t)h * LSEQ + (i0 + ty * 8)) * LSEQ + j0 + tx * 8;
#pragma unroll
            for (int r = 0; r < 8; r++) {
                float4 b0 = *(const float4*)(pbp + (size_t)r * LSEQ);
                float4 b1 = *(const float4*)(pbp + (size_t)r * LSEQ + 4);
                s[r][0] += gh * b0.x; s[r][1] += gh * b0.y;
                s[r][2] += gh * b0.z; s[r][3] += gh * b0.w;
                s[r][4] += gh * b1.x; s[r][5] += gh * b1.y;
                s[r][6] += gh * b1.z; s[r][7] += gh * b1.w;
            }
        }

#pragma unroll
        for (int r = 0; r < 8; r++) {
            float mr = s[r][0];
#pragma unroll
            for (int c = 1; c < 8; c++) mr = fmaxf(mr, s[r][c]);
#pragma unroll
            for (int off = 8; off >= 1; off >>= 1)
                mr = fmaxf(mr, __shfl_xor_sync(0xffffffffu, mr, off));
            const float m_new = fmaxf(m_i[r], mr);
            const float alpha = __expf(m_i[r] - m_new);
            m_i[r] = m_new;
            float sum = 0.0f;
#pragma unroll
            for (int c = 0; c < 8; c++) {
                const float p = __expf(s[r][c] - m_new);
                s[r][c] = p;
                sum += p;
            }
#pragma unroll
            for (int off = 8; off >= 1; off >>= 1)
                sum += __shfl_xor_sync(0xffffffffu, sum, off);
            l_i[r] = l_i[r] * alpha + sum;
#pragma unroll
            for (int c = 0; c < 4; c++) o[r][c] *= alpha;
            float4 p0, p1;
            p0.x = s[r][0]; p0.y = s[r][1]; p0.z = s[r][2]; p0.w = s[r][3];
            p1.x = s[r][4]; p1.y = s[r][5]; p1.z = s[r][6]; p1.w = s[r][7];
            *(float4*)&Ps[(ty * 8 + r) * PS_STR + tx * 8]     = p0;
            *(float4*)&Ps[(ty * 8 + r) * PS_STR + tx * 8 + 4] = p1;
        }
        __syncthreads();

#pragma unroll 4
        for (int j = 0; j < 128; j += 4) {
            float4 v0 = *(const float4*)&Vs[(j + 0) * VS_STR + tx * 4];
            float4 v1 = *(const float4*)&Vs[(j + 1) * VS_STR + tx * 4];
            float4 v2 = *(const float4*)&Vs[(j + 2) * VS_STR + tx * 4];
            float4 v3 = *(const float4*)&Vs[(j + 3) * VS_STR + tx * 4];
#pragma unroll
            for (int r = 0; r < 8; r++) {
                float4 p4 = *(const float4*)&Ps[(ty * 8 + r) * PS_STR + j];
                o[r][0] += p4.x * v0.x; o[r][1] += p4.x * v0.y;
                o[r][2] += p4.x * v0.z; o[r][3] += p4.x * v0.w;
                o[r][0] += p4.y * v1.x; o[r][1] += p4.y * v1.y;
                o[r][2] += p4.y * v1.z; o[r][3] += p4.y * v1.w;
                o[r][0] += p4.z * v2.x; o[r][1] += p4.z * v2.y;
                o[r][2] += p4.z * v2.z; o[r][3] += p4.z * v2.w;
                o[r][0] += p4.w * v3.x; o[r][1] += p4.w * v3.y;
                o[r][2] += p4.w * v3.z; o[r][3] += p4.w * v3.w;
            }
        }
        __syncthreads();
    }

#pragma unroll
    for (int r = 0; r < 8; r++) {
        const float inv = 1.0f / l_i[r];
        float4 ov;
        ov.x = o[r][0] * inv;
        ov.y = o[r][1] * inv;
        ov.z = o[r][2] * inv;
        ov.w = o[r][3] * inv;
        *(float4*)&g_att[(size_t)(i0 + ty * 8 + r) * DM + h * 64 + tx * 4] = ov;
    }
}

// ---------------------------------------------------------------------------
extern "C" void kernel_launch(void* const* d_in, const int* in_sizes, int n_in,
                              void* d_out, int out_size)
{
    const float* x    = (const float*)d_in[0];
    const float* pb   = (const float*)d_in[1];
    const float* gate = (const float*)d_in[2];
    const float* Wqkv = (const float*)d_in[3];
    const float* bqkv = (const float*)d_in[4];
    const float* Wout = (const float*)d_in[5];
    const float* bout = (const float*)d_in[6];
    float* out = (float*)d_out;

    // QKV projection: [2048,1024] @ [3072,1024]^T
    k_gemm_qkv<<<dim3((3 * DM) / 128, LSEQ / 128), 256>>>(x, Wqkv, bqkv);

    // Fused attention
    const int attn_smem = (2 * QS_N + 128 * VS_STR + 128 * PS_STR) * (int)sizeof(float); // 174080
    cudaFuncSetAttribute(k_attn, cudaFuncAttributeMaxDynamicSharedMemorySize, attn_smem);
    k_attn<<<dim3(LSEQ / 128, NH), 256, attn_smem>>>(pb, gate);

    // Output projection: [2048,1024] @ [1024,1024]^T
    k_gemm_out<<<dim3(DM / 128, LSEQ / 128), 256>>>(Wout, bout, out);
}

// round 12
// speedup vs baseline: 1.4245x; 1.0512x over previous
#include <cuda_runtime.h>
#include <math.h>

#define LSEQ 2048
#define DM 1024
#define NH 16

// Scratch (device globals: no allocation allowed in kernel_launch)
__device__ float g_qkv[LSEQ * 3 * DM];   // [i][s*1024 + h*64 + d]
__device__ float g_att[LSEQ * DM];       // [i][h*64+d]

// Bank-conflict-free column mapping: pad 4 floats every 32 columns.
// Range: smap(127) = 139, so row stride must be >= 140.
__device__ __forceinline__ int smap(int c) { return c + ((c >> 5) << 2); }

#define GSTR 140

// ---------------------------------------------------------------------------
// GEMM (R11-verbatim, PASSING, regs=127 — do not touch)
// C[M,N] = A[M,K] @ B[N,K]^T + bias[N]; BM=BN=128, BK=8, 8x8 microtile.
// ---------------------------------------------------------------------------
__device__ __forceinline__ void gemm_nt_bias(
    const float* __restrict__ A, const float* __restrict__ B,
    const float* __restrict__ bias, float* __restrict__ C,
    int N, int K)
{
    __shared__ __align__(16) float As[2][8][GSTR];
    __shared__ __align__(16) float Bs[2][8][GSTR];
    const int t  = threadIdx.x;
    const int tx = t & 15;
    const int ty = t >> 4;
    const int lr = t >> 1;
    const int lk = (t & 1) * 4;
    const int m0 = blockIdx.y * 128;
    const int n0 = blockIdx.x * 128;
    const int lrm = smap(lr);

    const float* Ap = A + (size_t)(m0 + lr) * K + lk;
    const float* Bp = B + (size_t)(n0 + lr) * K + lk;

    float4 a4 = *(const float4*)Ap;
    float4 b4 = *(const float4*)Bp;
    As[0][lk + 0][lrm] = a4.x; As[0][lk + 1][lrm] = a4.y;
    As[0][lk + 2][lrm] = a4.z; As[0][lk + 3][lrm] = a4.w;
    Bs[0][lk + 0][lrm] = b4.x; Bs[0][lk + 1][lrm] = b4.y;
    Bs[0][lk + 2][lrm] = b4.z; Bs[0][lk + 3][lrm] = b4.w;
    __syncthreads();

    float acc[8][8] = {};
    const int ra0 = smap(ty * 8);
    const int rb0 = smap(tx * 8);
    const int nk = K / 8;
    for (int kb = 0; kb < nk; kb++) {
        const int cur = kb & 1;
        if (kb + 1 < nk) {
            a4 = *(const float4*)(Ap + (size_t)(kb + 1) * 8);
            b4 = *(const float4*)(Bp + (size_t)(kb + 1) * 8);
        }
#pragma unroll
        for (int kk = 0; kk < 8; kk++) {
            float ra[8], rb[8];
            *(float4*)&ra[0] = *(const float4*)&As[cur][kk][ra0];
            *(float4*)&ra[4] = *(const float4*)&As[cur][kk][ra0 + 4];
            *(float4*)&rb[0] = *(const float4*)&Bs[cur][kk][rb0];
            *(float4*)&rb[4] = *(const float4*)&Bs[cur][kk][rb0 + 4];
#pragma unroll
            for (int r = 0; r < 8; r++)
#pragma unroll
                for (int c = 0; c < 8; c++)
                    acc[r][c] += ra[r] * rb[c];
        }
        if (kb + 1 < nk) {
            const int nxt = cur ^ 1;
            As[nxt][lk + 0][lrm] = a4.x; As[nxt][lk + 1][lrm] = a4.y;
            As[nxt][lk + 2][lrm] = a4.z; As[nxt][lk + 3][lrm] = a4.w;
            Bs[nxt][lk + 0][lrm] = b4.x; Bs[nxt][lk + 1][lrm] = b4.y;
            Bs[nxt][lk + 2][lrm] = b4.z; Bs[nxt][lk + 3][lrm] = b4.w;
        }
        __syncthreads();
    }

    float bi[8];
    *(float4*)&bi[0] = *(const float4*)(bias + n0 + tx * 8);
    *(float4*)&bi[4] = *(const float4*)(bias + n0 + tx * 8 + 4);
#pragma unroll
    for (int r = 0; r < 8; r++) {
        float* Crow = C + (size_t)(m0 + ty * 8 + r) * N + n0 + tx * 8;
        float4 o0, o1;
        o0.x = acc[r][0] + bi[0]; o0.y = acc[r][1] + bi[1];
        o0.z = acc[r][2] + bi[2]; o0.w = acc[r][3] + bi[3];
        o1.x = acc[r][4] + bi[4]; o1.y = acc[r][5] + bi[5];
        o1.z = acc[r][6] + bi[6]; o1.w = acc[r][7] + bi[7];
        *(float4*)Crow       = o0;
        *(float4*)(Crow + 4) = o1;
    }
}

__global__ void __launch_bounds__(256, 2)
k_gemm_qkv(const float* __restrict__ x, const float* __restrict__ W,
           const float* __restrict__ b)
{
    gemm_nt_bias(x, W, b, g_qkv, 3 * DM, DM);
}

__global__ void __launch_bounds__(256, 2)
k_gemm_out(const float* __restrict__ W, const float* __restrict__ b,
           float* __restrict__ out)
{
    gemm_nt_bias(g_att, W, b, out, DM, DM);
}

// ---------------------------------------------------------------------------
// Fused attention, j-tile 64 for 2 CTAs/SM.
// CTA = (128 i-rows, head); 32 j-tiles of 64.
// smem: Qs[64][140] (d-major, mapped i cols)
//       Ks[64][68]  (d-major: Ks[d][j])
//       Vs[64][68]  (j-major: Vs[j][d])
//       Ps[128][68] (i-major: Ps[i][j])
// total 105472 B -> 2 CTAs/SM.
// Thread (tx=t&15, ty=t>>4): S microtile 8(i) x 4(j); PV 8(i) x 4(d).
// ---------------------------------------------------------------------------
#define QK_STR 140
#define QS_N   (64 * QK_STR)
#define KV_STR 68
#define ATT_SMEM ((QS_N + 64 * KV_STR + 64 * KV_STR + 128 * KV_STR) * 4)

__global__ void __launch_bounds__(256, 2)
k_attn(const float* __restrict__ pb, const float* __restrict__ gate)
{
    extern __shared__ float smf[];
    float* Qs = smf;                      // [64][140]
    float* Ks = Qs + QS_N;                // [64 d][68]
    float* Vs = Ks + 64 * KV_STR;         // [64 j][68]
    float* Ps = Vs + 64 * KV_STR;         // [128 i][68]

    const int t  = threadIdx.x;
    const int tx = t & 15;
    const int ty = t >> 4;
    const int h  = blockIdx.y;
    const int i0 = blockIdx.x * 128;
    const float gh = gate[h];
    const float scale = 0.125f;

    // ---- load Q tile (pre-scaled), transposed to d-major, mapped i cols
    {
        const int lrow = t >> 1;        // 0..127
        const int ld0  = (t & 1) * 32;  // 0 or 32
        const int lrowm = smap(lrow);
        const float* src = g_qkv + (size_t)(i0 + lrow) * 3072 + h * 64 + ld0;
#pragma unroll
        for (int u = 0; u < 8; u++) {
            float4 q4 = *(const float4*)(src + u * 4);
            const int d = ld0 + u * 4;
            Qs[(d + 0) * QK_STR + lrowm] = q4.x * scale;
            Qs[(d + 1) * QK_STR + lrowm] = q4.y * scale;
            Qs[(d + 2) * QK_STR + lrowm] = q4.z * scale;
            Qs[(d + 3) * QK_STR + lrowm] = q4.w * scale;
        }
    }

    float m_i[8], l_i[8], o[8][4] = {};
#pragma unroll
    for (int r = 0; r < 8; r++) { m_i[r] = -1e30f; l_i[r] = 0.0f; }

    const int ra0 = smap(ty * 8);
    const int klrow = t >> 2;         // 0..63 (j)
    const int klcb  = (t & 3) * 16;   // d base
    const float* pbh = pb + (size_t)h * LSEQ * LSEQ;

    for (int jb = 0; jb < LSEQ / 64; jb++) {
        const int j0 = jb * 64;

        // ---- load K (transposed to d-major) and V (j-major)
        {
            const float* ksrc = g_qkv + (size_t)(j0 + klrow) * 3072 + 1024 + h * 64 + klcb;
            const float* vsrc = ksrc + 1024;
#pragma unroll
            for (int u = 0; u < 4; u++) {
                const int d = klcb + u * 4;
                float4 k4 = *(const float4*)(ksrc + u * 4);
                Ks[(d + 0) * KV_STR + klrow] = k4.x;
                Ks[(d + 1) * KV_STR + klrow] = k4.y;
                Ks[(d + 2) * KV_STR + klrow] = k4.z;
                Ks[(d + 3) * KV_STR + klrow] = k4.w;
                float4 v4 = *(const float4*)(vsrc + u * 4);
                *(float4*)&Vs[klrow * KV_STR + d] = v4;
            }
        }
        __syncthreads();

        // ---- S = (Q*scale) @ K^T : 8(i) x 4(j) per thread
        float s[8][4] = {};
#pragma unroll 8
        for (int kk = 0; kk < 64; kk++) {
            float ra[8], rb[4];
            *(float4*)&ra[0] = *(const float4*)&Qs[kk * QK_STR + ra0];
            *(float4*)&ra[4] = *(const float4*)&Qs[kk * QK_STR + ra0 + 4];
            *(float4*)&rb[0] = *(const float4*)&Ks[kk * KV_STR + tx * 4];
#pragma unroll
            for (int r = 0; r < 8; r++)
#pragma unroll
                for (int c = 0; c < 4; c++)
                    s[r][c] += ra[r] * rb[c];
        }

        // ---- + gate * pair_bias
        {
            const float* pbp = pbh + (size_t)(i0 + ty * 8) * LSEQ + j0 + tx * 4;
#pragma unroll
            for (int r = 0; r < 8; r++) {
                float4 b0 = *(const float4*)(pbp + (size_t)r * LSEQ);
                s[r][0] += gh * b0.x; s[r][1] += gh * b0.y;
                s[r][2] += gh * b0.z; s[r][3] += gh * b0.w;
            }
        }

        // ---- online softmax (row split over 16 tx lanes; 4-stage shfl)
#pragma unroll
        for (int r = 0; r < 8; r++) {
            float mr = fmaxf(fmaxf(s[r][0], s[r][1]), fmaxf(s[r][2], s[r][3]));
#pragma unroll
            for (int off = 8; off >= 1; off >>= 1)
                mr = fmaxf(mr, __shfl_xor_sync(0xffffffffu, mr, off));
            const float m_new = fmaxf(m_i[r], mr);
            const float alpha = __expf(m_i[r] - m_new);
            m_i[r] = m_new;
            float sum = 0.0f;
#pragma unroll
            for (int c = 0; c < 4; c++) {
                const float p = __expf(s[r][c] - m_new);
                s[r][c] = p;
                sum += p;
            }
#pragma unroll
            for (int off = 8; off >= 1; off >>= 1)
                sum += __shfl_xor_sync(0xffffffffu, sum, off);
            l_i[r] = l_i[r] * alpha + sum;
#pragma unroll
            for (int c = 0; c < 4; c++) o[r][c] *= alpha;
            float4 p0;
            p0.x = s[r][0]; p0.y = s[r][1]; p0.z = s[r][2]; p0.w = s[r][3];
            *(float4*)&Ps[(ty * 8 + r) * KV_STR + tx * 4] = p0;
        }
        __syncthreads();

        // ---- O += P @ V : 8(i) x 4(d) per thread, k = 64(j)
#pragma unroll 4
        for (int j = 0; j < 64; j += 4) {
            float4 v0 = *(const float4*)&Vs[(j + 0) * KV_STR + tx * 4];
            float4 v1 = *(const float4*)&Vs[(j + 1) * KV_STR + tx * 4];
            float4 v2 = *(const float4*)&Vs[(j + 2) * KV_STR + tx * 4];
            float4 v3 = *(const float4*)&Vs[(j + 3) * KV_STR + tx * 4];
#pragma unroll
            for (int r = 0; r < 8; r++) {
                float4 p4 = *(const float4*)&Ps[(ty * 8 + r) * KV_STR + j];
                o[r][0] += p4.x * v0.x; o[r][1] += p4.x * v0.y;
                o[r][2] += p4.x * v0.z; o[r][3] += p4.x * v0.w;
                o[r][0] += p4.y * v1.x; o[r][1] += p4.y * v1.y;
                o[r][2] += p4.y * v1.z; o[r][3] += p4.y * v1.w;
                o[r][0] += p4.z * v2.x; o[r][1] += p4.z * v2.y;
                o[r][2] += p4.z * v2.z; o[r][3] += p4.z * v2.w;
                o[r][0] += p4.w * v3.x; o[r][1] += p4.w * v3.y;
                o[r][2] += p4.w * v3.z; o[r][3] += p4.w * v3.w;
            }
        }
        __syncthreads();
    }

    // ---- normalize + write [i][h*64+d]
#pragma unroll
    for (int r = 0; r < 8; r++) {
        const float inv = 1.0f / l_i[r];
        float4 ov;
        ov.x = o[r][0] * inv;
        ov.y = o[r][1] * inv;
        ov.z = o[r][2] * inv;
        ov.w = o[r][3] * inv;
        *(float4*)&g_att[(size_t)(i0 + ty * 8 + r) * DM + h * 64 + tx * 4] = ov;
    }
}

// ---------------------------------------------------------------------------
extern "C" void kernel_launch(void* const* d_in, const int* in_sizes, int n_in,
                              void* d_out, int out_size)
{
    const float* x    = (const float*)d_in[0];
    const float* pb   = (const float*)d_in[1];
    const float* gate = (const float*)d_in[2];
    const float* Wqkv = (const float*)d_in[3];
    const float* bqkv = (const float*)d_in[4];
    const float* Wout = (const float*)d_in[5];
    const float* bout = (const float*)d_in[6];
    float* out = (float*)d_out;

    // QKV projection: [2048,1024] @ [3072,1024]^T
    k_gemm_qkv<<<dim3((3 * DM) / 128, LSEQ / 128), 256>>>(x, Wqkv, bqkv);

    // Fused attention (j-tile 64, 2 CTAs/SM)
    cudaFuncSetAttribute(k_attn, cudaFuncAttributeMaxDynamicSharedMemorySize, ATT_SMEM);
    k_attn<<<dim3(LSEQ / 128, NH), 256, ATT_SMEM>>>(pb, gate);

    // Output projection: [2048,1024] @ [1024,1024]^T
    k_gemm_out<<<dim3(DM / 128, LSEQ / 128), 256>>>(Wout, bout, out);
}